// round 1
// baseline (speedup 1.0000x reference)
#include <cuda_runtime.h>
#include <math.h>

#define D_MODEL 1024
#define D_FF    3072
#define NH      16
#define DH      64
#define SEQ     2048
#define BATCH   2
#define ROWS    (BATCH*SEQ)   // 4096
#define WINDOW  128

// ---------------- scratch (no allocs allowed) ----------------
__device__ float g_h  [ROWS * D_MODEL];        // LN output (reused for LN1 and LN2)
__device__ float g_qkv[ROWS * 3 * D_MODEL];    // QKV projection
__device__ float g_ctx[ROWS * D_MODEL];        // attention context
__device__ float g_x2 [ROWS * D_MODEL];        // x + attn residual
__device__ float g_ff [ROWS * D_FF];           // FF1 gelu output

// ---------------- LayerNorm ----------------
// one block per row, 256 threads, 4 floats/thread
__global__ void ln_kernel(const float* __restrict__ x, const float* __restrict__ g,
                          const float* __restrict__ bb, float* __restrict__ out) {
    int row = blockIdx.x;
    const float* xr = x + (size_t)row * D_MODEL;
    float* orow = out + (size_t)row * D_MODEL;
    int tid = threadIdx.x;
    float4 v = ((const float4*)xr)[tid];
    float s  = v.x + v.y + v.z + v.w;
    float s2 = v.x*v.x + v.y*v.y + v.z*v.z + v.w*v.w;
    __shared__ float rs[8], rs2[8];
    #pragma unroll
    for (int o = 16; o > 0; o >>= 1) {
        s  += __shfl_xor_sync(0xffffffffu, s,  o);
        s2 += __shfl_xor_sync(0xffffffffu, s2, o);
    }
    int w = tid >> 5, l = tid & 31;
    if (l == 0) { rs[w] = s; rs2[w] = s2; }
    __syncthreads();
    float ts = 0.f, ts2 = 0.f;
    #pragma unroll
    for (int i = 0; i < 8; i++) { ts += rs[i]; ts2 += rs2[i]; }
    float mu  = ts * (1.0f / D_MODEL);
    float var = ts2 * (1.0f / D_MODEL) - mu * mu;
    float inv = rsqrtf(var + 1e-5f);
    float4 gg = ((const float4*)g)[tid];
    float4 bv = ((const float4*)bb)[tid];
    float4 o;
    o.x = (v.x - mu) * inv * gg.x + bv.x;
    o.y = (v.y - mu) * inv * gg.y + bv.y;
    o.z = (v.z - mu) * inv * gg.z + bv.z;
    o.w = (v.w - mu) * inv * gg.w + bv.w;
    ((float4*)orow)[tid] = o;
}

// ---------------- GEMM C = A(MxK) * B(KxN) + epilogue ----------------
// EPI 0: C = acc + bias
// EPI 1: C = acc + bias + res
// EPI 2: C = gelu(acc + bias)
__device__ __forceinline__ float gelu_exact(float v) {
    return 0.5f * v * (1.0f + erff(v * 0.70710678118654752f));
}

template<int EPI>
__global__ void __launch_bounds__(256, 2) gemm_kernel(
    const float* __restrict__ A, const float* __restrict__ B,
    const float* __restrict__ bias, const float* __restrict__ res,
    float* __restrict__ C, int M, int N, int K)
{
    __shared__ float As[16][132];   // transposed A tile, padded
    __shared__ float Bs[16][132];
    int tid = threadIdx.x;
    int tx = tid & 15, ty = tid >> 4;
    int bm = blockIdx.y * 128, bn = blockIdx.x * 128;
    int a_r = tid >> 2, a_c = (tid & 3) << 2;    // A: 128 rows x 16 cols, 2 chunks
    int b_r = tid >> 5, b_c = (tid & 31) << 2;   // B: 16 rows x 128 cols, 2 chunks
    const float* Ag = A + (size_t)bm * K + a_c;
    const float* Bg = B + bn + b_c;
    float acc[8][8];
    #pragma unroll
    for (int i = 0; i < 8; i++)
        #pragma unroll
        for (int j = 0; j < 8; j++) acc[i][j] = 0.f;

    for (int k0 = 0; k0 < K; k0 += 16) {
        float4 a0 = *(const float4*)(Ag + (size_t)a_r * K + k0);
        float4 a1 = *(const float4*)(Ag + (size_t)(a_r + 64) * K + k0);
        float4 bv0 = *(const float4*)(Bg + (size_t)(k0 + b_r) * N);
        float4 bv1 = *(const float4*)(Bg + (size_t)(k0 + b_r + 8) * N);
        __syncthreads();
        As[a_c+0][a_r] = a0.x; As[a_c+1][a_r] = a0.y;
        As[a_c+2][a_r] = a0.z; As[a_c+3][a_r] = a0.w;
        As[a_c+0][a_r+64] = a1.x; As[a_c+1][a_r+64] = a1.y;
        As[a_c+2][a_r+64] = a1.z; As[a_c+3][a_r+64] = a1.w;
        *(float4*)&Bs[b_r][b_c]     = bv0;
        *(float4*)&Bs[b_r + 8][b_c] = bv1;
        __syncthreads();
        #pragma unroll
        for (int kk = 0; kk < 16; kk++) {
            float ra[8], rb[8];
            *(float4*)&ra[0] = *(const float4*)&As[kk][ty * 4];
            *(float4*)&ra[4] = *(const float4*)&As[kk][ty * 4 + 64];
            *(float4*)&rb[0] = *(const float4*)&Bs[kk][tx * 4];
            *(float4*)&rb[4] = *(const float4*)&Bs[kk][tx * 4 + 64];
            #pragma unroll
            for (int i = 0; i < 8; i++)
                #pragma unroll
                for (int j = 0; j < 8; j++)
                    acc[i][j] += ra[i] * rb[j];
        }
    }

    // epilogue
    float4 bias0 = *(const float4*)&bias[bn + tx * 4];
    float4 bias1 = *(const float4*)&bias[bn + 64 + tx * 4];
    float bs[8] = {bias0.x, bias0.y, bias0.z, bias0.w,
                   bias1.x, bias1.y, bias1.z, bias1.w};
    #pragma unroll
    for (int i = 0; i < 8; i++) {
        int r = bm + ((i < 4) ? (ty * 4 + i) : (64 + ty * 4 + i - 4));
        size_t ro = (size_t)r * N;
        float vv[8];
        #pragma unroll
        for (int j = 0; j < 8; j++) vv[j] = acc[i][j] + bs[j];
        if (EPI == 1) {
            float4 r0 = *(const float4*)&res[ro + bn + tx * 4];
            float4 r1 = *(const float4*)&res[ro + bn + 64 + tx * 4];
            vv[0] += r0.x; vv[1] += r0.y; vv[2] += r0.z; vv[3] += r0.w;
            vv[4] += r1.x; vv[5] += r1.y; vv[6] += r1.z; vv[7] += r1.w;
        }
        if (EPI == 2) {
            #pragma unroll
            for (int j = 0; j < 8; j++) vv[j] = gelu_exact(vv[j]);
        }
        float4 o0 = {vv[0], vv[1], vv[2], vv[3]};
        float4 o1 = {vv[4], vv[5], vv[6], vv[7]};
        *(float4*)&C[ro + bn + tx * 4]      = o0;
        *(float4*)&C[ro + bn + 64 + tx * 4] = o1;
    }
}

// ---------------- sliding-window attention ----------------
// grid: (SEQ/64, NH, BATCH); 256 threads
// Per block: 64 queries, 192-key band [q0-128, q0+64), all in smem.
#define QT   64
#define KT   192
#define SPAD 65
#define SSP  196

__global__ void attn_kernel(const float* __restrict__ qkv, float* __restrict__ ctx) {
    extern __shared__ float sm[];
    float* qs = sm;                        // QT x SPAD
    float* ks = sm + QT * SPAD;            // KT x SPAD
    float* vs = ks + KT * SPAD;            // KT x SPAD
    float* ss = sm;                        // QT x SSP  (overlaps qs+ks after sync)

    int tid = threadIdx.x;
    int tx = tid & 15, ty = tid >> 4;
    int q0 = blockIdx.x * QT;
    int h  = blockIdx.y;
    int b  = blockIdx.z;
    int k0 = q0 - WINDOW;
    const float* base = qkv + (size_t)b * SEQ * (3 * D_MODEL);

    // load Q tile
    for (int i = tid; i < QT * DH; i += 256) {
        int r = i / DH, d = i % DH;
        qs[r * SPAD + d] = base[(size_t)(q0 + r) * (3 * D_MODEL) + h * DH + d];
    }
    // load K,V band (zero-fill out-of-range)
    for (int i = tid; i < KT * DH; i += 256) {
        int r = i / DH, d = i % DH;
        int kj = k0 + r;
        float kv = 0.f, vv = 0.f;
        if (kj >= 0) {
            const float* rowp = base + (size_t)kj * (3 * D_MODEL);
            kv = rowp[D_MODEL     + h * DH + d];
            vv = rowp[2 * D_MODEL + h * DH + d];
        }
        ks[r * SPAD + d] = kv;
        vs[r * SPAD + d] = vv;
    }
    __syncthreads();

    // phase 1: scores.  thread (ty,tx): q in [ty*4, ty*4+4), j in [tx*12, tx*12+12)
    float sc[4][12];
    #pragma unroll
    for (int i = 0; i < 4; i++)
        #pragma unroll
        for (int jj = 0; jj < 12; jj++) sc[i][jj] = 0.f;

    for (int d = 0; d < DH; d++) {
        float a[4], bb[12];
        #pragma unroll
        for (int i = 0; i < 4; i++) a[i] = qs[(ty * 4 + i) * SPAD + d];
        #pragma unroll
        for (int jj = 0; jj < 12; jj++) bb[jj] = ks[(tx * 12 + jj) * SPAD + d];
        #pragma unroll
        for (int i = 0; i < 4; i++)
            #pragma unroll
            for (int jj = 0; jj < 12; jj++)
                sc[i][jj] += a[i] * bb[jj];
    }

    // mask + softmax (row reductions across the 16 tx lanes via shfl)
    float invsum[4];
    #pragma unroll
    for (int i = 0; i < 4; i++) {
        int q = ty * 4 + i;
        float mx = -3.4e38f;
        #pragma unroll
        for (int jj = 0; jj < 12; jj++) {
            int j = tx * 12 + jj;
            // allowed: j>q (within window) && j<=q+128 (causal) && key index >= 0
            bool ok = (j > q) && (j <= q + WINDOW) && (k0 + j >= 0);
            float sv = ok ? sc[i][jj] * 0.125f : -3.4e38f;
            sc[i][jj] = sv;
            mx = fmaxf(mx, sv);
        }
        #pragma unroll
        for (int o = 1; o < 16; o <<= 1)
            mx = fmaxf(mx, __shfl_xor_sync(0xffffffffu, mx, o));
        float su = 0.f;
        #pragma unroll
        for (int jj = 0; jj < 12; jj++) {
            float p = (sc[i][jj] > -1e37f) ? __expf(sc[i][jj] - mx) : 0.f;
            sc[i][jj] = p;
            su += p;
        }
        #pragma unroll
        for (int o = 1; o < 16; o <<= 1)
            su += __shfl_xor_sync(0xffffffffu, su, o);
        invsum[i] = 1.0f / su;
    }

    __syncthreads();  // all reads of qs/ks complete before ss overwrite
    #pragma unroll
    for (int i = 0; i < 4; i++)
        #pragma unroll
        for (int jj = 0; jj < 12; jj++)
            ss[(ty * 4 + i) * SSP + tx * 12 + jj] = sc[i][jj] * invsum[i];
    __syncthreads();

    // phase 2: ctx = P(64x192) @ V(192x64).  thread: q in [ty*4,+4), d in [tx*4,+4)
    float o[4][4];
    #pragma unroll
    for (int i = 0; i < 4; i++)
        #pragma unroll
        for (int l = 0; l < 4; l++) o[i][l] = 0.f;

    for (int j = 0; j < KT; j++) {
        float a[4], bv[4];
        #pragma unroll
        for (int i = 0; i < 4; i++) a[i] = ss[(ty * 4 + i) * SSP + j];
        #pragma unroll
        for (int l = 0; l < 4; l++) bv[l] = vs[j * SPAD + tx * 4 + l];
        #pragma unroll
        for (int i = 0; i < 4; i++)
            #pragma unroll
            for (int l = 0; l < 4; l++)
                o[i][l] += a[i] * bv[l];
    }
    #pragma unroll
    for (int i = 0; i < 4; i++) {
        size_t ro = (size_t)(b * SEQ + q0 + ty * 4 + i) * D_MODEL + h * DH + tx * 4;
        #pragma unroll
        for (int l = 0; l < 4; l++) ctx[ro + l] = o[i][l];
    }
}

// ---------------- launcher ----------------
extern "C" void kernel_launch(void* const* d_in, const int* in_sizes, int n_in,
                              void* d_out, int out_size) {
    const float* x     = (const float*)d_in[0];
    const float* w_qkv = (const float*)d_in[1];
    const float* b_qkv = (const float*)d_in[2];
    const float* w_out = (const float*)d_in[3];
    const float* b_out = (const float*)d_in[4];
    const float* w_ff1 = (const float*)d_in[5];
    const float* b_ff1 = (const float*)d_in[6];
    const float* w_ff2 = (const float*)d_in[7];
    const float* b_ff2 = (const float*)d_in[8];
    const float* ln1_g = (const float*)d_in[9];
    const float* ln1_b = (const float*)d_in[10];
    const float* ln2_g = (const float*)d_in[11];
    const float* ln2_b = (const float*)d_in[12];
    float* out = (float*)d_out;

    float *h, *qkv, *ctx, *x2, *ff;
    cudaGetSymbolAddress((void**)&h,   g_h);
    cudaGetSymbolAddress((void**)&qkv, g_qkv);
    cudaGetSymbolAddress((void**)&ctx, g_ctx);
    cudaGetSymbolAddress((void**)&x2,  g_x2);
    cudaGetSymbolAddress((void**)&ff,  g_ff);

    // 1. LN1
    ln_kernel<<<ROWS, 256>>>(x, ln1_g, ln1_b, h);

    // 2. QKV projection
    dim3 gqkv(3 * D_MODEL / 128, ROWS / 128);
    gemm_kernel<0><<<gqkv, 256>>>(h, w_qkv, b_qkv, nullptr, qkv,
                                  ROWS, 3 * D_MODEL, D_MODEL);

    // 3. sliding-window attention
    size_t smem = (size_t)(QT * SPAD + 2 * KT * SPAD) * sizeof(float);
    cudaFuncSetAttribute(attn_kernel, cudaFuncAttributeMaxDynamicSharedMemorySize,
                         (int)smem);
    attn_kernel<<<dim3(SEQ / QT, NH, BATCH), 256, smem>>>(qkv, ctx);

    // 4. out-projection + residual
    dim3 gout(D_MODEL / 128, ROWS / 128);
    gemm_kernel<1><<<gout, 256>>>(ctx, w_out, b_out, x, x2,
                                  ROWS, D_MODEL, D_MODEL);

    // 5. LN2
    ln_kernel<<<ROWS, 256>>>(x2, ln2_g, ln2_b, h);

    // 6. FF1 + exact GELU
    dim3 gff1(D_FF / 128, ROWS / 128);
    gemm_kernel<2><<<gff1, 256>>>(h, w_ff1, b_ff1, nullptr, ff,
                                  ROWS, D_FF, D_MODEL);

    // 7. FF2 + residual -> output
    dim3 gff2(D_MODEL / 128, ROWS / 128);
    gemm_kernel<1><<<gff2, 256>>>(ff, w_ff2, b_ff2, x2, out,
                                  ROWS, D_MODEL, D_FF);
}

// round 5
// speedup vs baseline: 1.6121x; 1.6121x over previous
#include <cuda_runtime.h>
#include <cuda_bf16.h>
#include <math.h>
#include <stdint.h>

#define D_MODEL 1024
#define D_FF    3072
#define NH      16
#define DH      64
#define SEQ     2048
#define BATCH   2
#define ROWS    (BATCH*SEQ)   // 4096
#define WINDOW  128

// ---------------- scratch ----------------
__device__ float g_h  [ROWS * D_MODEL];
__device__ float g_qkv[ROWS * 3 * D_MODEL];
__device__ float g_ctx[ROWS * D_MODEL];
__device__ float g_x2 [ROWS * D_MODEL];
__device__ float g_ff [ROWS * D_FF];

// transposed + bf16-split weights: [N][K] layout
#define WT_TOTAL 10485760
__device__ __nv_bfloat16 g_wh[WT_TOTAL];
__device__ __nv_bfloat16 g_wl[WT_TOTAL];

// ---------------- weight prep: W[K][N] fp32 -> Wt_hi/lo[N][K] bf16 ----------------
__global__ void prep_w(const float* __restrict__ W, __nv_bfloat16* __restrict__ Wh,
                       __nv_bfloat16* __restrict__ Wl, int K, int N) {
    __shared__ float t[32][33];
    int k0 = blockIdx.y * 32, n0 = blockIdx.x * 32;
    int tid = threadIdx.x;
    #pragma unroll
    for (int i = 0; i < 4; i++) {
        int lin = tid + 256 * i;
        int r = lin >> 5, c = lin & 31;
        t[r][c] = W[(size_t)(k0 + r) * N + n0 + c];
    }
    __syncthreads();
    #pragma unroll
    for (int i = 0; i < 4; i++) {
        int lin = tid + 256 * i;
        int n = lin >> 5, k = lin & 31;
        float x = t[k][n];
        __nv_bfloat16 hi = __float2bfloat16_rn(x);
        __nv_bfloat16 lo = __float2bfloat16_rn(x - __bfloat162float(hi));
        size_t o = (size_t)(n0 + n) * K + k0 + k;
        Wh[o] = hi;
        Wl[o] = lo;
    }
}

// ---------------- LayerNorm ----------------
__global__ void ln_kernel(const float* __restrict__ x, const float* __restrict__ g,
                          const float* __restrict__ bb, float* __restrict__ out) {
    int row = blockIdx.x;
    const float* xr = x + (size_t)row * D_MODEL;
    float* orow = out + (size_t)row * D_MODEL;
    int tid = threadIdx.x;
    float4 v = ((const float4*)xr)[tid];
    float s  = v.x + v.y + v.z + v.w;
    float s2 = v.x*v.x + v.y*v.y + v.z*v.z + v.w*v.w;
    __shared__ float rs[8], rs2[8];
    #pragma unroll
    for (int o = 16; o > 0; o >>= 1) {
        s  += __shfl_xor_sync(0xffffffffu, s,  o);
        s2 += __shfl_xor_sync(0xffffffffu, s2, o);
    }
    int w = tid >> 5, l = tid & 31;
    if (l == 0) { rs[w] = s; rs2[w] = s2; }
    __syncthreads();
    float ts = 0.f, ts2 = 0.f;
    #pragma unroll
    for (int i = 0; i < 8; i++) { ts += rs[i]; ts2 += rs2[i]; }
    float mu  = ts * (1.0f / D_MODEL);
    float var = ts2 * (1.0f / D_MODEL) - mu * mu;
    float inv = rsqrtf(var + 1e-5f);
    float4 gg = ((const float4*)g)[tid];
    float4 bv = ((const float4*)bb)[tid];
    float4 o;
    o.x = (v.x - mu) * inv * gg.x + bv.x;
    o.y = (v.y - mu) * inv * gg.y + bv.y;
    o.z = (v.z - mu) * inv * gg.z + bv.z;
    o.w = (v.w - mu) * inv * gg.w + bv.w;
    ((float4*)orow)[tid] = o;
}

// ---------------- bf16x3 mma.sync GEMM ----------------
// C(M,N) = A(M,K) @ B(K,N) + bias [+res | gelu]
// A fp32 [M][K]; B pre-split bf16 [N][K] (hi+lo).
// C ≈ Ah*Bh + Ah*Bl + Al*Bh  (fp32 accum).
// CTA 128x128, BK=32, 8 warps (4m x 2n), warp tile 32x64.

#define BKP 40
#define BUF_ELEMS 20480            // 4 tiles * 128 * BKP
#define OFF_AH 0
#define OFF_AL 5120
#define OFF_BH 10240
#define OFF_BL 15360

#define MMA_BF16(d, a, b) \
    asm volatile("mma.sync.aligned.m16n8k16.row.col.f32.bf16.bf16.f32 " \
        "{%0,%1,%2,%3}, {%4,%5,%6,%7}, {%8,%9}, {%0,%1,%2,%3};" \
        : "+f"((d)[0]), "+f"((d)[1]), "+f"((d)[2]), "+f"((d)[3]) \
        : "r"((a)[0]), "r"((a)[1]), "r"((a)[2]), "r"((a)[3]), \
          "r"((b)[0]), "r"((b)[1]))

__device__ __forceinline__ uint32_t pack_bf2(float x, float y) {
    __nv_bfloat16 a = __float2bfloat16_rn(x);
    __nv_bfloat16 b = __float2bfloat16_rn(y);
    return (uint32_t)__bfloat16_as_ushort(a) | ((uint32_t)__bfloat16_as_ushort(b) << 16);
}

__device__ __forceinline__ float gelu_exact(float v) {
    return 0.5f * v * (1.0f + erff(v * 0.70710678118654752f));
}

template<int EPI>  // 0: +bias  1: +bias+res  2: gelu(+bias)
__global__ void __launch_bounds__(256, 1) gemm_mma(
    const float* __restrict__ A, const __nv_bfloat16* __restrict__ Bh,
    const __nv_bfloat16* __restrict__ Bl,
    const float* __restrict__ bias, const float* __restrict__ res,
    float* __restrict__ C, int M, int N, int K)
{
    extern __shared__ __nv_bfloat16 sm[];
    int tid = threadIdx.x;
    int wid = tid >> 5, lane = tid & 31;
    int g = lane >> 2, tg = lane & 3;
    int wm = wid >> 1, wn = wid & 1;

    int bm = blockIdx.y * 128, bn = blockIdx.x * 128;
    int ns = K >> 5;

    float acc[2][8][4];
    #pragma unroll
    for (int mi = 0; mi < 2; mi++)
        #pragma unroll
        for (int ni = 0; ni < 8; ni++)
            #pragma unroll
            for (int q = 0; q < 4; q++) acc[mi][ni][q] = 0.f;

    // gmem load indices
    int ar = tid >> 3, aq = tid & 7;        // A: rows ar+32i (4 iters), float4 col aq
    int br = tid >> 2, bq = tid & 3;        // B: rows br+64i (2 iters), uint4 chunk bq

    const float* Ag = A + (size_t)(bm + ar) * K + aq * 4;
    const __nv_bfloat16* Bhg = Bh + (size_t)(bn + br) * K + bq * 8;
    const __nv_bfloat16* Blg = Bl + (size_t)(bn + br) * K + bq * 8;

    float4 av[4];
    uint4 bhv[2], blv[2];

    // prologue: load stage 0
    #pragma unroll
    for (int i = 0; i < 4; i++) av[i] = *(const float4*)(Ag + (size_t)(32 * i) * K);
    #pragma unroll
    for (int i = 0; i < 2; i++) {
        bhv[i] = *(const uint4*)(Bhg + (size_t)(64 * i) * K);
        blv[i] = *(const uint4*)(Blg + (size_t)(64 * i) * K);
    }
    {
        __nv_bfloat16* buf = sm;
        #pragma unroll
        for (int i = 0; i < 4; i++) {
            int row = ar + 32 * i;
            float4 v = av[i];
            float hx = __bfloat162float(__float2bfloat16_rn(v.x));
            float hy = __bfloat162float(__float2bfloat16_rn(v.y));
            float hz = __bfloat162float(__float2bfloat16_rn(v.z));
            float hw = __bfloat162float(__float2bfloat16_rn(v.w));
            uint2 h = {pack_bf2(v.x, v.y), pack_bf2(v.z, v.w)};
            uint2 lo = {pack_bf2(v.x - hx, v.y - hy), pack_bf2(v.z - hz, v.w - hw)};
            *(uint2*)&buf[OFF_AH + row * BKP + aq * 4] = h;
            *(uint2*)&buf[OFF_AL + row * BKP + aq * 4] = lo;
        }
        #pragma unroll
        for (int i = 0; i < 2; i++) {
            int row = br + 64 * i;
            *(uint4*)&buf[OFF_BH + row * BKP + bq * 8] = bhv[i];
            *(uint4*)&buf[OFF_BL + row * BKP + bq * 8] = blv[i];
        }
    }
    __syncthreads();

    for (int s = 0; s < ns; s++) {
        // prefetch next stage to regs
        if (s + 1 < ns) {
            int k0 = (s + 1) << 5;
            #pragma unroll
            for (int i = 0; i < 4; i++)
                av[i] = *(const float4*)(Ag + (size_t)(32 * i) * K + k0);
            #pragma unroll
            for (int i = 0; i < 2; i++) {
                bhv[i] = *(const uint4*)(Bhg + (size_t)(64 * i) * K + k0);
                blv[i] = *(const uint4*)(Blg + (size_t)(64 * i) * K + k0);
            }
        }

        // mma on current buffer
        const uint32_t* sp = (const uint32_t*)(sm + (size_t)(s & 1) * BUF_ELEMS);
        #pragma unroll
        for (int ks = 0; ks < 32; ks += 16) {
            uint32_t ah[2][4], al[2][4], bh[8][2], bl[8][2];
            #pragma unroll
            for (int mi = 0; mi < 2; mi++) {
                int r0 = (wm * 32 + mi * 16 + g) * BKP + ks + tg * 2;
                int r1 = r0 + 8 * BKP;
                ah[mi][0] = sp[(OFF_AH + r0) >> 1];
                ah[mi][1] = sp[(OFF_AH + r1) >> 1];
                ah[mi][2] = sp[(OFF_AH + r0 + 8) >> 1];
                ah[mi][3] = sp[(OFF_AH + r1 + 8) >> 1];
                al[mi][0] = sp[(OFF_AL + r0) >> 1];
                al[mi][1] = sp[(OFF_AL + r1) >> 1];
                al[mi][2] = sp[(OFF_AL + r0 + 8) >> 1];
                al[mi][3] = sp[(OFF_AL + r1 + 8) >> 1];
            }
            #pragma unroll
            for (int ni = 0; ni < 8; ni++) {
                int rn = (wn * 64 + ni * 8 + g) * BKP + ks + tg * 2;
                bh[ni][0] = sp[(OFF_BH + rn) >> 1];
                bh[ni][1] = sp[(OFF_BH + rn + 8) >> 1];
                bl[ni][0] = sp[(OFF_BL + rn) >> 1];
                bl[ni][1] = sp[(OFF_BL + rn + 8) >> 1];
            }
            #pragma unroll
            for (int mi = 0; mi < 2; mi++)
                #pragma unroll
                for (int ni = 0; ni < 8; ni++) {
                    MMA_BF16(acc[mi][ni], ah[mi], bh[ni]);
                    MMA_BF16(acc[mi][ni], ah[mi], bl[ni]);
                    MMA_BF16(acc[mi][ni], al[mi], bh[ni]);
                }
        }
        __syncthreads();

        // store next stage
        if (s + 1 < ns) {
            __nv_bfloat16* buf = sm + (size_t)((s + 1) & 1) * BUF_ELEMS;
            #pragma unroll
            for (int i = 0; i < 4; i++) {
                int row = ar + 32 * i;
                float4 v = av[i];
                float hx = __bfloat162float(__float2bfloat16_rn(v.x));
                float hy = __bfloat162float(__float2bfloat16_rn(v.y));
                float hz = __bfloat162float(__float2bfloat16_rn(v.z));
                float hw = __bfloat162float(__float2bfloat16_rn(v.w));
                uint2 h = {pack_bf2(v.x, v.y), pack_bf2(v.z, v.w)};
                uint2 lo = {pack_bf2(v.x - hx, v.y - hy), pack_bf2(v.z - hz, v.w - hw)};
                *(uint2*)&buf[OFF_AH + row * BKP + aq * 4] = h;
                *(uint2*)&buf[OFF_AL + row * BKP + aq * 4] = lo;
            }
            #pragma unroll
            for (int i = 0; i < 2; i++) {
                int row = br + 64 * i;
                *(uint4*)&buf[OFF_BH + row * BKP + bq * 8] = bhv[i];
                *(uint4*)&buf[OFF_BL + row * BKP + bq * 8] = blv[i];
            }
            __syncthreads();
        }
    }

    // epilogue
    #pragma unroll
    for (int mi = 0; mi < 2; mi++) {
        int r0 = bm + wm * 32 + mi * 16 + g;
        int r1 = r0 + 8;
        #pragma unroll
        for (int ni = 0; ni < 8; ni++) {
            int cn = bn + wn * 64 + ni * 8 + tg * 2;
            float2 bv = *(const float2*)&bias[cn];
            float x0 = acc[mi][ni][0] + bv.x;
            float x1 = acc[mi][ni][1] + bv.y;
            float x2 = acc[mi][ni][2] + bv.x;
            float x3 = acc[mi][ni][3] + bv.y;
            size_t o0 = (size_t)r0 * N + cn;
            size_t o1 = (size_t)r1 * N + cn;
            if (EPI == 1) {
                float2 q0 = *(const float2*)&res[o0];
                float2 q1 = *(const float2*)&res[o1];
                x0 += q0.x; x1 += q0.y; x2 += q1.x; x3 += q1.y;
            }
            if (EPI == 2) {
                x0 = gelu_exact(x0); x1 = gelu_exact(x1);
                x2 = gelu_exact(x2); x3 = gelu_exact(x3);
            }
            float2 s0 = {x0, x1}, s1 = {x2, x3};
            *(float2*)&C[o0] = s0;
            *(float2*)&C[o1] = s1;
        }
    }
}

// ---------------- sliding-window attention (unchanged, verified) ----------------
#define QT   64
#define KT   192
#define SPAD 65
#define SSP  196

__global__ void attn_kernel(const float* __restrict__ qkv, float* __restrict__ ctx) {
    extern __shared__ float smf[];
    float* qs = smf;
    float* ks = smf + QT * SPAD;
    float* vs = ks + KT * SPAD;
    float* ss = smf;

    int tid = threadIdx.x;
    int tx = tid & 15, ty = tid >> 4;
    int q0 = blockIdx.x * QT;
    int h  = blockIdx.y;
    int b  = blockIdx.z;
    int k0 = q0 - WINDOW;
    const float* base = qkv + (size_t)b * SEQ * (3 * D_MODEL);

    for (int i = tid; i < QT * DH; i += 256) {
        int r = i / DH, d = i % DH;
        qs[r * SPAD + d] = base[(size_t)(q0 + r) * (3 * D_MODEL) + h * DH + d];
    }
    for (int i = tid; i < KT * DH; i += 256) {
        int r = i / DH, d = i % DH;
        int kj = k0 + r;
        float kv = 0.f, vv = 0.f;
        if (kj >= 0) {
            const float* rowp = base + (size_t)kj * (3 * D_MODEL);
            kv = rowp[D_MODEL     + h * DH + d];
            vv = rowp[2 * D_MODEL + h * DH + d];
        }
        ks[r * SPAD + d] = kv;
        vs[r * SPAD + d] = vv;
    }
    __syncthreads();

    float sc[4][12];
    #pragma unroll
    for (int i = 0; i < 4; i++)
        #pragma unroll
        for (int jj = 0; jj < 12; jj++) sc[i][jj] = 0.f;

    for (int d = 0; d < DH; d++) {
        float a[4], bb[12];
        #pragma unroll
        for (int i = 0; i < 4; i++) a[i] = qs[(ty * 4 + i) * SPAD + d];
        #pragma unroll
        for (int jj = 0; jj < 12; jj++) bb[jj] = ks[(tx * 12 + jj) * SPAD + d];
        #pragma unroll
        for (int i = 0; i < 4; i++)
            #pragma unroll
            for (int jj = 0; jj < 12; jj++)
                sc[i][jj] += a[i] * bb[jj];
    }

    float invsum[4];
    #pragma unroll
    for (int i = 0; i < 4; i++) {
        int q = ty * 4 + i;
        float mx = -3.4e38f;
        #pragma unroll
        for (int jj = 0; jj < 12; jj++) {
            int j = tx * 12 + jj;
            bool ok = (j > q) && (j <= q + WINDOW) && (k0 + j >= 0);
            float sv = ok ? sc[i][jj] * 0.125f : -3.4e38f;
            sc[i][jj] = sv;
            mx = fmaxf(mx, sv);
        }
        #pragma unroll
        for (int o = 1; o < 16; o <<= 1)
            mx = fmaxf(mx, __shfl_xor_sync(0xffffffffu, mx, o));
        float su = 0.f;
        #pragma unroll
        for (int jj = 0; jj < 12; jj++) {
            float p = (sc[i][jj] > -1e37f) ? __expf(sc[i][jj] - mx) : 0.f;
            sc[i][jj] = p;
            su += p;
        }
        #pragma unroll
        for (int o = 1; o < 16; o <<= 1)
            su += __shfl_xor_sync(0xffffffffu, su, o);
        invsum[i] = 1.0f / su;
    }

    __syncthreads();
    #pragma unroll
    for (int i = 0; i < 4; i++)
        #pragma unroll
        for (int jj = 0; jj < 12; jj++)
            ss[(ty * 4 + i) * SSP + tx * 12 + jj] = sc[i][jj] * invsum[i];
    __syncthreads();

    float o[4][4];
    #pragma unroll
    for (int i = 0; i < 4; i++)
        #pragma unroll
        for (int l = 0; l < 4; l++) o[i][l] = 0.f;

    for (int j = 0; j < KT; j++) {
        float a[4], bv[4];
        #pragma unroll
        for (int i = 0; i < 4; i++) a[i] = ss[(ty * 4 + i) * SSP + j];
        #pragma unroll
        for (int l = 0; l < 4; l++) bv[l] = vs[j * SPAD + tx * 4 + l];
        #pragma unroll
        for (int i = 0; i < 4; i++)
            #pragma unroll
            for (int l = 0; l < 4; l++)
                o[i][l] += a[i] * bv[l];
    }
    #pragma unroll
    for (int i = 0; i < 4; i++) {
        size_t ro = (size_t)(b * SEQ + q0 + ty * 4 + i) * D_MODEL + h * DH + tx * 4;
        #pragma unroll
        for (int l = 0; l < 4; l++) ctx[ro + l] = o[i][l];
    }
}

// ---------------- launcher ----------------
#define GEMM_SMEM (2 * BUF_ELEMS * 2)   // 81920 bytes

extern "C" void kernel_launch(void* const* d_in, const int* in_sizes, int n_in,
                              void* d_out, int out_size) {
    const float* x     = (const float*)d_in[0];
    const float* w_qkv = (const float*)d_in[1];
    const float* b_qkv = (const float*)d_in[2];
    const float* w_out = (const float*)d_in[3];
    const float* b_out = (const float*)d_in[4];
    const float* w_ff1 = (const float*)d_in[5];
    const float* b_ff1 = (const float*)d_in[6];
    const float* w_ff2 = (const float*)d_in[7];
    const float* b_ff2 = (const float*)d_in[8];
    const float* ln1_g = (const float*)d_in[9];
    const float* ln1_b = (const float*)d_in[10];
    const float* ln2_g = (const float*)d_in[11];
    const float* ln2_b = (const float*)d_in[12];
    float* out = (float*)d_out;

    float *h, *qkv, *ctx, *x2, *ff;
    __nv_bfloat16 *wh, *wl;
    cudaGetSymbolAddress((void**)&h,   g_h);
    cudaGetSymbolAddress((void**)&qkv, g_qkv);
    cudaGetSymbolAddress((void**)&ctx, g_ctx);
    cudaGetSymbolAddress((void**)&x2,  g_x2);
    cudaGetSymbolAddress((void**)&ff,  g_ff);
    cudaGetSymbolAddress((void**)&wh,  g_wh);
    cudaGetSymbolAddress((void**)&wl,  g_wl);

    __nv_bfloat16 *wh_qkv = wh,           *wl_qkv = wl;
    __nv_bfloat16 *wh_out = wh + 3145728, *wl_out = wl + 3145728;
    __nv_bfloat16 *wh_ff1 = wh + 4194304, *wl_ff1 = wl + 4194304;
    __nv_bfloat16 *wh_ff2 = wh + 7340032, *wl_ff2 = wl + 7340032;

    cudaFuncSetAttribute(gemm_mma<0>, cudaFuncAttributeMaxDynamicSharedMemorySize, GEMM_SMEM);
    cudaFuncSetAttribute(gemm_mma<1>, cudaFuncAttributeMaxDynamicSharedMemorySize, GEMM_SMEM);
    cudaFuncSetAttribute(gemm_mma<2>, cudaFuncAttributeMaxDynamicSharedMemorySize, GEMM_SMEM);

    // 0. weight prep (transpose + bf16 split)
    prep_w<<<dim3(3 * D_MODEL / 32, D_MODEL / 32), 256>>>(w_qkv, wh_qkv, wl_qkv, D_MODEL, 3 * D_MODEL);
    prep_w<<<dim3(D_MODEL / 32, D_MODEL / 32), 256>>>(w_out, wh_out, wl_out, D_MODEL, D_MODEL);
    prep_w<<<dim3(D_FF / 32, D_MODEL / 32), 256>>>(w_ff1, wh_ff1, wl_ff1, D_MODEL, D_FF);
    prep_w<<<dim3(D_MODEL / 32, D_FF / 32), 256>>>(w_ff2, wh_ff2, wl_ff2, D_FF, D_MODEL);

    // 1. LN1
    ln_kernel<<<ROWS, 256>>>(x, ln1_g, ln1_b, h);

    // 2. QKV projection
    gemm_mma<0><<<dim3(3 * D_MODEL / 128, ROWS / 128), 256, GEMM_SMEM>>>(
        h, wh_qkv, wl_qkv, b_qkv, nullptr, qkv, ROWS, 3 * D_MODEL, D_MODEL);

    // 3. sliding-window attention
    size_t smem = (size_t)(QT * SPAD + 2 * KT * SPAD) * sizeof(float);
    cudaFuncSetAttribute(attn_kernel, cudaFuncAttributeMaxDynamicSharedMemorySize, (int)smem);
    attn_kernel<<<dim3(SEQ / QT, NH, BATCH), 256, smem>>>(qkv, ctx);

    // 4. out-projection + residual
    gemm_mma<1><<<dim3(D_MODEL / 128, ROWS / 128), 256, GEMM_SMEM>>>(
        ctx, wh_out, wl_out, b_out, x, x2, ROWS, D_MODEL, D_MODEL);

    // 5. LN2
    ln_kernel<<<ROWS, 256>>>(x2, ln2_g, ln2_b, h);

    // 6. FF1 + exact GELU
    gemm_mma<2><<<dim3(D_FF / 128, ROWS / 128), 256, GEMM_SMEM>>>(
        h, wh_ff1, wl_ff1, b_ff1, nullptr, ff, ROWS, D_FF, D_MODEL);

    // 7. FF2 + residual -> output
    gemm_mma<1><<<dim3(D_MODEL / 128, ROWS / 128), 256, GEMM_SMEM>>>(
        ff, wh_ff2, wl_ff2, b_ff2, x2, out, ROWS, D_MODEL, D_FF);
}